// round 1
// baseline (speedup 1.0000x reference)
#include <cuda_runtime.h>
#include <math.h>

#define NBATCH 16
#define NEDGE  131072
#define NN1    8192
#define KP1    410
#define KP2    205
#define NN2    6560      /* 16*410 */
#define NN3    3280      /* 16*205 */
#define EMB    512
#define F3     1536
#define E1TOT  (NEDGE+NN1)
#define E2TOT  (NEDGE+NN2)
#define CDIV(a,b) (((a)+(b)-1)/(b))

/* ---------------- scratch (static device globals; no allocs) -------------- */
__device__ float    d_xp1 [NN1*F3];
__device__ float    d_asn1[NN1*3], d_adn1[NN1*3];
__device__ unsigned d_emax1[NN1*3];
__device__ float    d_den1[NN1*3];
__device__ float    d_ex1 [E1TOT*3];
__device__ int      d_cnt1[NN1], d_fill1[NN1], d_rp1[NN1+1], d_eid1[E1TOT];
__device__ float    d_gat1[NN1*F3];
__device__ float    d_h1  [NN1*EMB];
__device__ float    d_y1  [NN1*EMB];
__device__ float    d_sc1 [NN1];
__device__ int      d_map1[NN1];
__device__ float    d_hp1 [NN2*EMB];
__device__ float    d_x1c [NBATCH*1024];
__device__ int      d_s2  [NEDGE], d_t2[NEDGE];

__device__ float    d_xp2 [NN2*F3];
__device__ float    d_asn2[NN2*3], d_adn2[NN2*3];
__device__ unsigned d_emax2[NN2*3];
__device__ float    d_den2[NN2*3];
__device__ float    d_ex2 [E2TOT*3];
__device__ int      d_cnt2[NN2], d_fill2[NN2], d_rp2[NN2+1], d_eid2[E2TOT];
__device__ float    d_gat2[NN2*F3];
__device__ float    d_h2  [NN2*EMB];
__device__ float    d_y2  [NN2*EMB];
__device__ float    d_sc2 [NN2];
__device__ float    d_hp2 [NN3*EMB];
__device__ float    d_x2c [NBATCH*1024];

__device__ float    d_bsum[EMB], d_bsq[EMB];
__device__ float    d_rnorm[1];
__device__ float    d_t1  [NBATCH*512];

/* ------------------------------- helpers ---------------------------------- */
__device__ __forceinline__ unsigned f2o(float f){
    unsigned u = __float_as_uint(f);
    return (u & 0x80000000u) ? ~u : (u | 0x80000000u);
}
__device__ __forceinline__ float o2f(unsigned e){
    return (e & 0x80000000u) ? __uint_as_float(e & 0x7FFFFFFFu)
                             : __uint_as_float(~e);
}

__global__ void k_fill_u32(unsigned* __restrict__ p, unsigned v, int n){
    int i = blockIdx.x*blockDim.x + threadIdx.x;
    if(i < n) p[i] = v;
}

/* xp1 = x @ W1  (K=3) */
__global__ void k_xw1(const float* __restrict__ x, const float* __restrict__ W){
    int idx = blockIdx.x*blockDim.x + threadIdx.x;
    if(idx >= NN1*F3) return;
    int n = idx / F3, j = idx - n*F3;
    d_xp1[idx] = x[n*3+0]*W[j] + x[n*3+1]*W[F3+j] + x[n*3+2]*W[2*F3+j];
}

/* a_s[n,h] = <xp[n,h,:], att_s[h,:]>, same for a_d. one warp per (n,h) */
__global__ void k_attdot(const float* __restrict__ xp, const float* __restrict__ as_,
                         const float* __restrict__ ad_, float* __restrict__ asn,
                         float* __restrict__ adn, int Nn){
    int w = (blockIdx.x*blockDim.x + threadIdx.x) >> 5;
    int lane = threadIdx.x & 31;
    if(w >= Nn*3) return;
    int n = w/3, h = w - n*3;
    const float* row = xp + (size_t)n*F3 + h*EMB;
    float s = 0.f, d = 0.f;
    for(int c = lane; c < EMB; c += 32){ float v = row[c]; s += v*as_[h*EMB+c]; d += v*ad_[h*EMB+c]; }
    for(int o = 16; o; o >>= 1){ s += __shfl_down_sync(~0u,s,o); d += __shfl_down_sync(~0u,d,o); }
    if(!lane){ asn[n*3+h] = s; adn[n*3+h] = d; }
}

/* per-edge e = leaky_relu(a_s[src]+a_d[tgt]); segment max via encoded atomicMax */
__global__ void k_edge_max(const int* __restrict__ sA, const int* __restrict__ tA,
                           const float* __restrict__ asn, const float* __restrict__ adn,
                           unsigned* __restrict__ emax, int nSelf){
    int i = blockIdx.x*blockDim.x + threadIdx.x;
    if(i >= NEDGE + nSelf) return;
    int s, t;
    if(i < NEDGE){ s = sA[i]; t = tA[i]; if((s|t) < 0) return; }
    else { s = t = i - NEDGE; }
    #pragma unroll
    for(int h = 0; h < 3; h++){
        float e = asn[s*3+h] + adn[t*3+h];
        e = e > 0.f ? e : 0.2f*e;
        atomicMax(&emax[t*3+h], f2o(e));
    }
}

/* ex = exp(e - max); den += ex */
__global__ void k_edge_ex(const int* __restrict__ sA, const int* __restrict__ tA,
                          const float* __restrict__ asn, const float* __restrict__ adn,
                          const unsigned* __restrict__ emax, float* __restrict__ ex,
                          float* __restrict__ den, int nSelf){
    int i = blockIdx.x*blockDim.x + threadIdx.x;
    if(i >= NEDGE + nSelf) return;
    int s, t;
    if(i < NEDGE){ s = sA[i]; t = tA[i]; if((s|t) < 0) return; }
    else { s = t = i - NEDGE; }
    #pragma unroll
    for(int h = 0; h < 3; h++){
        float e = asn[s*3+h] + adn[t*3+h];
        e = e > 0.f ? e : 0.2f*e;
        float v = expf(e - o2f(emax[t*3+h]));
        ex[i*3+h] = v;
        atomicAdd(&den[t*3+h], v);
    }
}

__global__ void k_count(const int* __restrict__ sA, const int* __restrict__ tA,
                        int* __restrict__ cnt, int nSelf){
    int i = blockIdx.x*blockDim.x + threadIdx.x;
    if(i >= NEDGE + nSelf) return;
    int s, t;
    if(i < NEDGE){ s = sA[i]; t = tA[i]; if((s|t) < 0) return; }
    else { s = t = i - NEDGE; }
    atomicAdd(&cnt[t], 1);
}

/* exclusive scan of n (<=8192) counts, single block of 1024 */
__global__ void k_scan(const int* __restrict__ cnt, int* __restrict__ rp, int n){
    __shared__ int part[1024];
    int t = threadIdx.x;
    int per = (n + 1023) >> 10;
    int base = t * per;
    int loc[8]; int s = 0;
    for(int k = 0; k < per; k++){ int idx = base+k; int c = (idx<n)? cnt[idx]:0; loc[k]=s; s+=c; }
    part[t] = s; __syncthreads();
    for(int off = 1; off < 1024; off <<= 1){
        int v = (t >= off) ? part[t-off] : 0;
        __syncthreads(); part[t] += v; __syncthreads();
    }
    int pre = (t == 0) ? 0 : part[t-1];
    for(int k = 0; k < per; k++){ int idx = base+k; if(idx < n) rp[idx] = pre + loc[k]; }
    if(t == 1023) rp[n] = part[1023];
}

__global__ void k_scatter(const int* __restrict__ sA, const int* __restrict__ tA,
                          const int* __restrict__ rp, int* __restrict__ fill,
                          int* __restrict__ eid, int nSelf){
    int i = blockIdx.x*blockDim.x + threadIdx.x;
    if(i >= NEDGE + nSelf) return;
    int s, t;
    if(i < NEDGE){ s = sA[i]; t = tA[i]; if((s|t) < 0) return; }
    else { s = t = i - NEDGE; }
    int pos = atomicAdd(&fill[t], 1);
    eid[rp[t] + pos] = i;
}

/* out[n,:] = bias + sum_edges alpha[i,h] * xp[src, h*512+c]  — one block / node */
__global__ void k_agg(const int* __restrict__ rp, const int* __restrict__ eid,
                      const int* __restrict__ sA, const float* __restrict__ xp,
                      const float* __restrict__ ex, const float* __restrict__ den,
                      const float* __restrict__ bias, float* __restrict__ out){
    int n = blockIdx.x, t = threadIdx.x;     /* 256 threads */
    float rd0 = 1.f/fmaxf(den[n*3+0], 1e-16f);
    float rd1 = 1.f/fmaxf(den[n*3+1], 1e-16f);
    float rd2 = 1.f/fmaxf(den[n*3+2], 1e-16f);
    float a0=0,a1=0,b0=0,b1=0,c0=0,c1=0;
    int beg = rp[n], end = rp[n+1];
    for(int e = beg; e < end; e++){
        int i = eid[e];
        int s = (i < NEDGE) ? sA[i] : (i - NEDGE);
        float w0 = ex[i*3+0]*rd0, w1 = ex[i*3+1]*rd1, w2 = ex[i*3+2]*rd2;
        const float* r = xp + (size_t)s*F3;
        a0 += w0*r[t];        a1 += w0*r[t+256];
        b0 += w1*r[t+512];    b1 += w1*r[t+768];
        c0 += w2*r[t+1024];   c1 += w2*r[t+1280];
    }
    float* o = out + (size_t)n*F3;
    o[t]      = a0 + bias[t];      o[t+256]  = a1 + bias[t+256];
    o[t+512]  = b0 + bias[t+512];  o[t+768]  = b1 + bias[t+768];
    o[t+1024] = c0 + bias[t+1024]; o[t+1280] = c1 + bias[t+1280];
}

/* fp32 GEMM: C[M,N] = A[M,K]@B[K,N] (+bias, optional relu). 64x64 tile, 4x4/thr */
template<int RELU>
__global__ void k_gemm(const float* __restrict__ A, const float* __restrict__ B,
                       const float* __restrict__ bias, float* __restrict__ C,
                       int M, int N, int K){
    __shared__ __align__(16) float sA[16][68];
    __shared__ __align__(16) float sB[16][68];
    int bm = blockIdx.y*64, bn = blockIdx.x*64;
    int tid = threadIdx.x;
    int tx = tid & 15, ty = tid >> 4;
    float acc[4][4] = {};
    int arow = tid >> 2, ac4 = (tid & 3) << 2;
    int brow = tid >> 4, bc4 = (tid & 15) << 2;
    for(int k0 = 0; k0 < K; k0 += 16){
        float4 va = make_float4(0,0,0,0);
        if(bm + arow < M) va = *(const float4*)(A + (size_t)(bm+arow)*K + k0 + ac4);
        sA[ac4+0][arow]=va.x; sA[ac4+1][arow]=va.y; sA[ac4+2][arow]=va.z; sA[ac4+3][arow]=va.w;
        float4 vb = *(const float4*)(B + (size_t)(k0+brow)*N + bn + bc4);
        *(float4*)&sB[brow][bc4] = vb;
        __syncthreads();
        #pragma unroll
        for(int k = 0; k < 16; k++){
            float4 a = *(const float4*)&sA[k][ty<<2];
            float4 b = *(const float4*)&sB[k][tx<<2];
            float ar[4] = {a.x,a.y,a.z,a.w}, br[4] = {b.x,b.y,b.z,b.w};
            #pragma unroll
            for(int r = 0; r < 4; r++)
                #pragma unroll
                for(int c = 0; c < 4; c++) acc[r][c] += ar[r]*br[c];
        }
        __syncthreads();
    }
    #pragma unroll
    for(int r = 0; r < 4; r++){
        int row = bm + (ty<<2) + r;
        if(row < M){
            #pragma unroll
            for(int c = 0; c < 4; c++){
                int col = bn + (tx<<2) + c;
                float v = acc[r][c] + (bias ? bias[col] : 0.f);
                if(RELU) v = fmaxf(v, 0.f);
                C[(size_t)row*N + col] = v;
            }
        }
    }
}

__global__ void k_bnstats(const float* __restrict__ h, int M){
    int t = threadIdx.x;                      /* 256 */
    int r0 = blockIdx.x*64;
    float s0=0,q0=0,s1=0,q1=0;
    int rend = min(r0+64, M);
    for(int r = r0; r < rend; r++){
        float v0 = h[(size_t)r*EMB + t], v1 = h[(size_t)r*EMB + t + 256];
        s0 += v0; q0 += v0*v0; s1 += v1; q1 += v1*v1;
    }
    atomicAdd(&d_bsum[t], s0);     atomicAdd(&d_bsq[t], q0);
    atomicAdd(&d_bsum[t+256], s1); atomicAdd(&d_bsq[t+256], q1);
}

__global__ void k_rnorm(const float* __restrict__ p){
    __shared__ float red[512];
    int t = threadIdx.x;
    float v = p[t]; red[t] = v*v; __syncthreads();
    for(int o = 256; o; o >>= 1){ if(t < o) red[t] += red[t+o]; __syncthreads(); }
    if(!t) d_rnorm[0] = rsqrtf(red[0]);
}

/* BN (batch stats) -> y; score = tanh(<y,p> / ||p||). one block / row */
__global__ void k_bnapply(const float* __restrict__ h, const float* __restrict__ g,
                          const float* __restrict__ be, const float* __restrict__ p,
                          float* __restrict__ y, float* __restrict__ score, int M){
    int row = blockIdx.x, t = threadIdx.x;    /* 256 */
    float invM = 1.f/(float)M;
    float dot = 0.f;
    #pragma unroll
    for(int u = 0; u < 2; u++){
        int c = t + u*256;
        float m = d_bsum[c]*invM;
        float v = d_bsq[c]*invM - m*m;
        float yy = (h[(size_t)row*EMB + c] - m)*rsqrtf(v + 1e-5f)*g[c] + be[c];
        y[(size_t)row*EMB + c] = yy;
        dot += yy*p[c];
    }
    __shared__ float red[256];
    red[t] = dot; __syncthreads();
    for(int o = 128; o; o >>= 1){ if(t < o) red[t] += red[t+o]; __syncthreads(); }
    if(!t) score[row] = tanhf(red[0]*d_rnorm[0]);
}

/* per-graph top-k via 512-wide bitonic sort; writes scaled pooled rows + mapping */
__global__ void k_topk(const float* __restrict__ score, const float* __restrict__ y,
                       float* __restrict__ hp, int* map, int n_per, int keep){
    int b = blockIdx.x, t = threadIdx.x;      /* 512 */
    __shared__ float sk[512]; __shared__ int si[512];
    sk[t] = (t < n_per) ? score[b*n_per + t] : -3.0e38f;
    si[t] = t;
    __syncthreads();
    for(int k = 2; k <= 512; k <<= 1)
        for(int j = k>>1; j > 0; j >>= 1){
            int x = t ^ j;
            if(x > t){
                bool up = ((t & k) == 0);
                float a = sk[t], c = sk[x];
                bool sw = up ? (a < c) : (a > c);
                if(sw){ sk[t]=c; sk[x]=a; int ti=si[t]; si[t]=si[x]; si[x]=ti; }
            }
            __syncthreads();
        }
    if(map && t < n_per) map[b*n_per + t] = -1;
    __syncthreads();
    if(map && t < keep) map[b*n_per + si[t]] = b*keep + t;
    for(int r = 0; r < keep; r++){
        int node = b*n_per + si[r];
        float s = sk[r];
        hp[((size_t)(b*keep + r))*EMB + t] = y[(size_t)node*EMB + t]*s;
    }
}

__global__ void k_poolcat(const float* __restrict__ hp, float* __restrict__ xc, int keep){
    int b = blockIdx.x, t = threadIdx.x;      /* 512 */
    float mx = -3.0e38f, sm = 0.f;
    for(int r = 0; r < keep; r++){
        float v = hp[((size_t)(b*keep + r))*EMB + t];
        mx = fmaxf(mx, v); sm += v;
    }
    xc[b*1024 + t] = mx;
    xc[b*1024 + 512 + t] = sm/(float)keep;
}

__global__ void k_relabel(const int* __restrict__ ei){
    int i = blockIdx.x*blockDim.x + threadIdx.x;
    if(i >= NEDGE) return;
    d_s2[i] = d_map1[ei[i]];
    d_t2[i] = d_map1[ei[NEDGE + i]];
}

__global__ void k_mlp1(const float* __restrict__ Wl1, const float* __restrict__ bl1){
    int b = blockIdx.x, j = threadIdx.x;      /* 512 */
    __shared__ float xg[1024];
    xg[j]     = d_x1c[b*1024 + j]       + d_x2c[b*1024 + j];
    xg[j+512] = d_x1c[b*1024 + 512 + j] + d_x2c[b*1024 + 512 + j];
    __syncthreads();
    float s = bl1[j];
    for(int k = 0; k < 1024; k++) s += xg[k]*Wl1[k*512 + j];
    d_t1[b*512 + j] = fmaxf(s, 0.f);
}

__global__ void k_mlp2(const float* __restrict__ Wl2, const float* __restrict__ bl2,
                       float* __restrict__ out){
    int b = blockIdx.x, o = threadIdx.x;      /* 256 */
    __shared__ float tt[512];
    tt[o] = d_t1[b*512 + o]; tt[o+256] = d_t1[b*512 + o + 256];
    __syncthreads();
    float s = bl2[o];
    for(int k = 0; k < 512; k++) s += tt[k]*Wl2[k*256 + o];
    out[b*256 + o] = s;
}

/* -------------------------------- host ------------------------------------ */
#define GETP(T, v, sym_) T* v; { void* _p; cudaGetSymbolAddress(&_p, sym_); v = (T*)_p; }

extern "C" void kernel_launch(void* const* d_in, const int* in_sizes, int n_in,
                              void* d_out, int out_size){
    (void)in_sizes; (void)n_in; (void)out_size;
    const float* x   = (const float*)d_in[0];
    const int*   ei  = (const int*)  d_in[1];
    const float* W1  = (const float*)d_in[2];
    const float* as1 = (const float*)d_in[3];
    const float* ad1 = (const float*)d_in[4];
    const float* bc1 = (const float*)d_in[5];
    const float* Wh1 = (const float*)d_in[6];
    const float* bh1 = (const float*)d_in[7];
    const float* g1  = (const float*)d_in[8];
    const float* be1 = (const float*)d_in[9];
    const float* p1  = (const float*)d_in[10];
    const float* W2  = (const float*)d_in[11];
    const float* as2 = (const float*)d_in[12];
    const float* ad2 = (const float*)d_in[13];
    const float* bc2 = (const float*)d_in[14];
    const float* Wh2 = (const float*)d_in[15];
    const float* bh2 = (const float*)d_in[16];
    const float* g2  = (const float*)d_in[17];
    const float* be2 = (const float*)d_in[18];
    const float* p2  = (const float*)d_in[19];
    const float* Wl1 = (const float*)d_in[20];
    const float* bl1 = (const float*)d_in[21];
    const float* Wl2 = (const float*)d_in[22];
    const float* bl2 = (const float*)d_in[23];

    GETP(float, xp1, d_xp1)   GETP(float, asn1, d_asn1) GETP(float, adn1, d_adn1)
    GETP(unsigned, emax1, d_emax1) GETP(float, den1, d_den1) GETP(float, ex1, d_ex1)
    GETP(int, cnt1, d_cnt1)   GETP(int, fill1, d_fill1) GETP(int, rp1, d_rp1)
    GETP(int, eid1, d_eid1)   GETP(float, gat1, d_gat1) GETP(float, h1, d_h1)
    GETP(float, y1, d_y1)     GETP(float, sc1, d_sc1)   GETP(int, map1, d_map1)
    GETP(float, hp1, d_hp1)   GETP(float, x1c, d_x1c)
    GETP(int, s2, d_s2)       GETP(int, t2, d_t2)
    GETP(float, xp2, d_xp2)   GETP(float, asn2, d_asn2) GETP(float, adn2, d_adn2)
    GETP(unsigned, emax2, d_emax2) GETP(float, den2, d_den2) GETP(float, ex2, d_ex2)
    GETP(int, cnt2, d_cnt2)   GETP(int, fill2, d_fill2) GETP(int, rp2, d_rp2)
    GETP(int, eid2, d_eid2)   GETP(float, gat2, d_gat2) GETP(float, h2, d_h2)
    GETP(float, y2, d_y2)     GETP(float, sc2, d_sc2)   GETP(float, hp2, d_hp2)
    GETP(float, x2c, d_x2c)
    GETP(float, bsum, d_bsum) GETP(float, bsq, d_bsq)

    /* ---- layer 1 ---- */
    k_fill_u32<<<CDIV(NN1*3,256),256>>>(emax1, 0u, NN1*3);
    k_fill_u32<<<CDIV(NN1*3,256),256>>>((unsigned*)den1, 0u, NN1*3);
    k_fill_u32<<<CDIV(NN1,256),256>>>((unsigned*)cnt1, 0u, NN1);
    k_fill_u32<<<CDIV(NN1,256),256>>>((unsigned*)fill1, 0u, NN1);

    k_xw1<<<CDIV(NN1*F3,256),256>>>(x, W1);
    k_attdot<<<CDIV(NN1*3*32,256),256>>>(xp1, as1, ad1, asn1, adn1, NN1);
    k_edge_max<<<CDIV(E1TOT,256),256>>>(ei, ei+NEDGE, asn1, adn1, emax1, NN1);
    k_edge_ex<<<CDIV(E1TOT,256),256>>>(ei, ei+NEDGE, asn1, adn1, emax1, ex1, den1, NN1);
    k_count<<<CDIV(E1TOT,256),256>>>(ei, ei+NEDGE, cnt1, NN1);
    k_scan<<<1,1024>>>(cnt1, rp1, NN1);
    k_scatter<<<CDIV(E1TOT,256),256>>>(ei, ei+NEDGE, rp1, fill1, eid1, NN1);
    k_agg<<<NN1,256>>>(rp1, eid1, ei, xp1, ex1, den1, bc1, gat1);

    k_gemm<1><<<dim3(512/64, NN1/64),256>>>(gat1, Wh1, bh1, h1, NN1, 512, F3);

    k_fill_u32<<<2,256>>>((unsigned*)bsum, 0u, EMB);
    k_fill_u32<<<2,256>>>((unsigned*)bsq, 0u, EMB);
    k_bnstats<<<CDIV(NN1,64),256>>>(h1, NN1);
    k_rnorm<<<1,512>>>(p1);
    k_bnapply<<<NN1,256>>>(h1, g1, be1, p1, y1, sc1, NN1);
    k_topk<<<NBATCH,512>>>(sc1, y1, hp1, map1, 512, KP1);
    k_poolcat<<<NBATCH,512>>>(hp1, x1c, KP1);
    k_relabel<<<CDIV(NEDGE,256),256>>>(ei);

    /* ---- layer 2 ---- */
    k_fill_u32<<<CDIV(NN2*3,256),256>>>(emax2, 0u, NN2*3);
    k_fill_u32<<<CDIV(NN2*3,256),256>>>((unsigned*)den2, 0u, NN2*3);
    k_fill_u32<<<CDIV(NN2,256),256>>>((unsigned*)cnt2, 0u, NN2);
    k_fill_u32<<<CDIV(NN2,256),256>>>((unsigned*)fill2, 0u, NN2);

    k_gemm<0><<<dim3(F3/64, CDIV(NN2,64)),256>>>(hp1, W2, (const float*)nullptr, xp2, NN2, F3, 512);
    k_attdot<<<CDIV(NN2*3*32,256),256>>>(xp2, as2, ad2, asn2, adn2, NN2);
    k_edge_max<<<CDIV(E2TOT,256),256>>>(s2, t2, asn2, adn2, emax2, NN2);
    k_edge_ex<<<CDIV(E2TOT,256),256>>>(s2, t2, asn2, adn2, emax2, ex2, den2, NN2);
    k_count<<<CDIV(E2TOT,256),256>>>(s2, t2, cnt2, NN2);
    k_scan<<<1,1024>>>(cnt2, rp2, NN2);
    k_scatter<<<CDIV(E2TOT,256),256>>>(s2, t2, rp2, fill2, eid2, NN2);
    k_agg<<<NN2,256>>>(rp2, eid2, s2, xp2, ex2, den2, bc2, gat2);

    k_gemm<1><<<dim3(512/64, CDIV(NN2,64)),256>>>(gat2, Wh2, bh2, h2, NN2, 512, F3);

    k_fill_u32<<<2,256>>>((unsigned*)bsum, 0u, EMB);
    k_fill_u32<<<2,256>>>((unsigned*)bsq, 0u, EMB);
    k_bnstats<<<CDIV(NN2,64),256>>>(h2, NN2);
    k_rnorm<<<1,512>>>(p2);
    k_bnapply<<<NN2,256>>>(h2, g2, be2, p2, y2, sc2, NN2);
    k_topk<<<NBATCH,512>>>(sc2, y2, hp2, (int*)nullptr, KP1, KP2);
    k_poolcat<<<NBATCH,512>>>(hp2, x2c, KP2);

    /* ---- head ---- */
    k_mlp1<<<NBATCH,512>>>(Wl1, bl1);
    k_mlp2<<<NBATCH,256>>>(Wl2, bl2, (float*)d_out);
}